// round 15
// baseline (speedup 1.0000x reference)
#include <cuda_runtime.h>
#include <cuda_fp16.h>
#include <cstdint>

// ============================================================
// Problem constants
// ============================================================
#define NUM_T 8192
#define DIM_H 2048
#define NUM_E 8
#define PADT  17408          // 16384 assignments + per-expert 128-pad

// GEMM tile: 128x128 CTA, 8 warps of 64x32, 2 CTAs/SM (4 warps/SMSP)
#define BM 128
#define BN 128
#define BK 64                // 64 fp16 = 128 B = one swizzled row
#define STAGES 3
#define NT_TILES (DIM_H / BN)   // 16
#define GEMM_CTAS 296           // 148 SMs x 2 (persistent)

// ============================================================
// Device scratch (allocation-free rule: static __device__ arrays)
// ============================================================
__device__ int   g_cnt[NUM_E];
__device__ int   g_tile;                                 // persistent work counter
__device__ int   g_toklist[NUM_E * NUM_T];
__device__ int   g_tk_e[NUM_T * 2];
__device__ int   g_tk_pos[NUM_T * 2];
__device__ float g_tk_w[NUM_T * 2];
__device__ __half g_wh[(size_t)NUM_E * DIM_H * DIM_H];   // 67 MB fp16 weights
__device__ __half g_xh[(size_t)PADT * DIM_H];            // gathered A (fp16)
__device__ __half g_y[(size_t)PADT * DIM_H];             // expert outputs (fp16)

// ============================================================
// PTX helpers (base sm_103-safe: sm_80-era instructions only)
// ============================================================
__device__ __forceinline__ uint32_t smem_to_u32(const void* p) {
    uint32_t a;
    asm("{ .reg .u64 t; cvta.to.shared.u64 t, %1; cvt.u32.u64 %0, t; }" : "=r"(a) : "l"(p));
    return a;
}

#define CP_ASYNC16(s, g) \
    asm volatile("cp.async.cg.shared.global [%0], [%1], 16;" :: "r"(s), "l"(g))
#define CP_COMMIT() asm volatile("cp.async.commit_group;" ::: "memory")
#define CP_WAIT(n)  asm volatile("cp.async.wait_group %0;" :: "n"(n) : "memory")

__device__ __forceinline__ void ldsm_x4(uint32_t (&r)[4], uint32_t addr) {
    asm volatile("ldmatrix.sync.aligned.m8n8.x4.shared.b16 {%0,%1,%2,%3}, [%4];"
        : "=r"(r[0]), "=r"(r[1]), "=r"(r[2]), "=r"(r[3]) : "r"(addr));
}
__device__ __forceinline__ void mma16816(float (&d)[4], const uint32_t (&a)[4],
                                         uint32_t b0, uint32_t b1) {
    asm volatile(
        "mma.sync.aligned.m16n8k16.row.col.f32.f16.f16.f32 "
        "{%0,%1,%2,%3}, {%4,%5,%6,%7}, {%8,%9}, {%0,%1,%2,%3};"
        : "+f"(d[0]), "+f"(d[1]), "+f"(d[2]), "+f"(d[3])
        : "r"(a[0]), "r"(a[1]), "r"(a[2]), "r"(a[3]), "r"(b0), "r"(b1));
}

// ============================================================
// Kernel 1: zero counters + tile counter
// ============================================================
__global__ void init_kernel() {
    if (threadIdx.x < NUM_E) g_cnt[threadIdx.x] = 0;
    if (threadIdx.x == NUM_E) g_tile = 0;
}

// ============================================================
// Kernel 2: router (one warp per token)
// ============================================================
__global__ __launch_bounds__(256) void router_kernel(
    const float* __restrict__ x, const float* __restrict__ gw,
    float* __restrict__ logits_out)
{
    int gwarp = (blockIdx.x * blockDim.x + threadIdx.x) >> 5;
    int lane  = threadIdx.x & 31;
    if (gwarp >= NUM_T) return;
    int t = gwarp;

    const float4* xr = reinterpret_cast<const float4*>(x + (size_t)t * DIM_H);
    const float4* g4 = reinterpret_cast<const float4*>(gw);

    float acc[NUM_E];
#pragma unroll
    for (int e = 0; e < NUM_E; e++) acc[e] = 0.f;

#pragma unroll 4
    for (int i = 0; i < 16; i++) {
        float4 xv = __ldg(&xr[lane + i * 32]);
#pragma unroll
        for (int e = 0; e < NUM_E; e++) {
            float4 gv = __ldg(&g4[e * 512 + lane + i * 32]);
            acc[e] += xv.x * gv.x + xv.y * gv.y + xv.z * gv.z + xv.w * gv.w;
        }
    }
#pragma unroll
    for (int e = 0; e < NUM_E; e++) {
#pragma unroll
        for (int o = 16; o > 0; o >>= 1)
            acc[e] += __shfl_xor_sync(0xFFFFFFFFu, acc[e], o);
    }

    if (lane == 0) {
        float* lo = logits_out + (size_t)t * NUM_E;
#pragma unroll
        for (int e = 0; e < NUM_E; e++) lo[e] = acc[e];

        int e1 = 0; float l1 = acc[0];
#pragma unroll
        for (int e = 1; e < NUM_E; e++) if (acc[e] > l1) { l1 = acc[e]; e1 = e; }
        int e2 = -1; float l2 = -3.4e38f;
#pragma unroll
        for (int e = 0; e < NUM_E; e++) if (e != e1 && acc[e] > l2) { l2 = acc[e]; e2 = e; }

        float w1 = 1.0f / (1.0f + expf(l2 - l1));   // sigmoid(l1-l2)
        float w2 = 1.0f - w1;

        int p1 = atomicAdd(&g_cnt[e1], 1);
        g_toklist[e1 * NUM_T + p1] = t;
        g_tk_e[2 * t + 0] = e1; g_tk_pos[2 * t + 0] = p1; g_tk_w[2 * t + 0] = w1;

        int p2 = atomicAdd(&g_cnt[e2], 1);
        g_toklist[e2 * NUM_T + p2] = t;
        g_tk_e[2 * t + 1] = e2; g_tk_pos[2 * t + 1] = p2; g_tk_w[2 * t + 1] = w2;
    }
}

// ============================================================
// Kernel 3: convert W fp32 -> fp16 (runs on forked stream)
// ============================================================
__global__ __launch_bounds__(256) void convert_w_kernel(const float* __restrict__ ew) {
    size_t i = (size_t)blockIdx.x * 256 + threadIdx.x;  // float4 index
    float4 v = __ldg(reinterpret_cast<const float4*>(ew) + i);
    __half2* o = reinterpret_cast<__half2*>(g_wh) + 2 * i;
    o[0] = __floats2half2_rn(v.x, v.y);
    o[1] = __floats2half2_rn(v.z, v.w);
}

// ============================================================
// Kernel 4: gather tokens into expert order, fp32 -> fp16
// (prefix offsets computed inline from g_cnt)
// ============================================================
__global__ __launch_bounds__(256) void gatherx_kernel(const float* __restrict__ x) {
    int slot = blockIdx.x;

    int e = -1, local = 0, cnt_e = 0;
    {
        int off = 0;
#pragma unroll
        for (int k = 0; k < NUM_E; k++) {
            int cnt = g_cnt[k];
            int sz = ((cnt + BM - 1) / BM) * BM;
            if (e < 0 && slot < off + sz) { e = k; local = slot - off; cnt_e = cnt; }
            off += sz;
        }
        if (e < 0) return;   // beyond padded total
    }
    int tok = (local < cnt_e) ? g_toklist[e * NUM_T + local] : -1;

    __half2* hi = reinterpret_cast<__half2*>(g_xh + (size_t)slot * DIM_H);
    int tid = threadIdx.x;

    if (tok < 0) {
        __half2 z = __floats2half2_rn(0.f, 0.f);
#pragma unroll
        for (int i = 0; i < 2; i++) {
            int c = tid + i * 256;                // float4 index 0..511
            hi[2 * c] = z; hi[2 * c + 1] = z;
        }
        return;
    }
    const float4* xr = reinterpret_cast<const float4*>(x + (size_t)tok * DIM_H);
#pragma unroll
    for (int i = 0; i < 2; i++) {
        int c = tid + i * 256;
        float4 v = __ldg(&xr[c]);
        hi[2 * c]     = __floats2half2_rn(v.x, v.y);
        hi[2 * c + 1] = __floats2half2_rn(v.z, v.w);
    }
}

// ============================================================
// Kernel 5: PERSISTENT pipelined mma.sync GEMM
// 296 CTAs steal tiles via atomic counter (mtile-major order so
// consecutive tiles share the A tile through L2).
// CTA tile 128x128, 3-stage cp.async, 8 warps of 64x32.
// ============================================================
#define SM_A 0
#define SM_B (BM * 128)                    // 16384
#define STAGE_BYTES (BM * 128 + BN * 128)  // 32768
#define GEMM_SMEM (STAGES * STAGE_BYTES)   // 98304

__device__ __forceinline__ void issue_stage(
    uint32_t sbase, const __half* Ah, const __half* Bw, int koff, int tid)
{
#pragma unroll
    for (int i = 0; i < 4; i++) {
        int ch = tid + i * 256;
        int row = ch >> 3, c = ch & 7;
        uint32_t soff = row * 128 + ((c ^ (row & 7)) * 16);
        const char* ga = (const char*)(Ah + (size_t)row * DIM_H + koff) + c * 16;
        CP_ASYNC16(sbase + SM_A + soff, ga);
    }
#pragma unroll
    for (int i = 0; i < 4; i++) {
        int ch = tid + i * 256;
        int row = ch >> 3, c = ch & 7;
        uint32_t soff = row * 128 + ((c ^ (row & 7)) * 16);
        const char* gb = (const char*)(Bw + (size_t)row * DIM_H + koff) + c * 16;
        CP_ASYNC16(sbase + SM_B + soff, gb);
    }
    CP_COMMIT();
}

__global__ __launch_bounds__(256, 2) void moe_gemm_kernel() {
    extern __shared__ char smem[];
    __shared__ int s_tile;
    uint32_t sb = smem_to_u32(smem);
    int tid = threadIdx.x, wid = tid >> 5, lane = tid & 31;

    // live tile count from g_cnt (uniform loads, all CTAs identical)
    int nmt = 0;
#pragma unroll
    for (int k = 0; k < NUM_E; k++) nmt += (g_cnt[k] + BM - 1) / BM;
    int ntotal = nmt * NT_TILES;

    int wm0 = (wid & 1) * 64;
    int wn0 = (wid >> 1) * 32;
    int lrow = lane & 15;
    int lhalf = lane >> 4;

    for (;;) {
        if (tid == 0) s_tile = atomicAdd(&g_tile, 1);
        __syncthreads();
        int tt = s_tile;
        if (tt >= ntotal) break;
        int mtile = tt >> 4;              // mtile-major: adjacent tts share A
        int ntile = tt & (NT_TILES - 1);

        // inline tile table: find expert owning this mtile
        int e = -1, mrow = 0;
        {
            int tacc = 0, off = 0;
#pragma unroll
            for (int k = 0; k < NUM_E; k++) {
                int tiles = (g_cnt[k] + BM - 1) / BM;
                if (e < 0 && mtile < tacc + tiles) { e = k; mrow = off + (mtile - tacc) * BM; }
                tacc += tiles;
                off += tiles * BM;
            }
        }

        const __half* Ah = g_xh + (size_t)mrow * DIM_H;
        const __half* Bw = g_wh + (size_t)e * DIM_H * DIM_H + (size_t)(ntile * BN) * DIM_H;

        // prologue
#pragma unroll
        for (int s = 0; s < STAGES - 1; s++)
            issue_stage(sb + s * STAGE_BYTES, Ah, Bw, s * BK, tid);

        // warp tile 64x32: acc[4 mf][4 nf][4]
        float acc[4][4][4];
#pragma unroll
        for (int a = 0; a < 4; a++)
#pragma unroll
            for (int b = 0; b < 4; b++)
#pragma unroll
                for (int c = 0; c < 4; c++) acc[a][b][c] = 0.f;

        const int KT = DIM_H / BK;   // 32
        for (int kc = 0; kc < KT; kc++) {
            CP_WAIT(STAGES - 2);
            __syncthreads();
            uint32_t sbase = sb + (kc % STAGES) * STAGE_BYTES;

            if (kc + STAGES - 1 < KT)
                issue_stage(sb + ((kc + STAGES - 1) % STAGES) * STAGE_BYTES,
                            Ah, Bw, (kc + STAGES - 1) * BK, tid);
            else
                CP_COMMIT();   // keep group accounting uniform

#pragma unroll
            for (int ks = 0; ks < 4; ks++) {
                uint32_t ah[4][4], bf[2][4];
                int c = ks * 2 + lhalf;
#pragma unroll
                for (int mf = 0; mf < 4; mf++) {
                    int row = wm0 + mf * 16 + lrow;
                    ldsm_x4(ah[mf], sbase + SM_A + row * 128 + ((c ^ (row & 7)) * 16));
                }
#pragma unroll
                for (int nb = 0; nb < 2; nb++) {
                    int row = wn0 + nb * 16 + lrow;
                    ldsm_x4(bf[nb], sbase + SM_B + row * 128 + ((c ^ (row & 7)) * 16));
                }
#pragma unroll
                for (int mf = 0; mf < 4; mf++)
#pragma unroll
                    for (int nb = 0; nb < 2; nb++) {
                        mma16816(acc[mf][2 * nb],     ah[mf], bf[nb][0], bf[nb][2]);
                        mma16816(acc[mf][2 * nb + 1], ah[mf], bf[nb][1], bf[nb][3]);
                    }
            }
        }

        // epilogue: fp16 half2 stores into g_y
        int r0 = lane >> 2;
        int c0 = (lane & 3) * 2;
#pragma unroll
        for (int mf = 0; mf < 4; mf++)
#pragma unroll
            for (int nf = 0; nf < 4; nf++)
#pragma unroll
                for (int h = 0; h < 2; h++) {
                    int row = mrow + wm0 + mf * 16 + r0 + 8 * h;
                    int col = ntile * BN + wn0 + nf * 8 + c0;
                    __half2 v = __floats2half2_rn(acc[mf][nf][2 * h], acc[mf][nf][2 * h + 1]);
                    *reinterpret_cast<__half2*>(g_y + (size_t)row * DIM_H + col) = v;
                }

        __syncthreads();   // all warps done with smem + s_tile before next steal
    }
}

// ============================================================
// Kernel 6: combine fp16 y slots into final fp32 out
// ============================================================
__global__ __launch_bounds__(256) void combine_kernel(float* __restrict__ out) {
    int idx = blockIdx.x * 256 + threadIdx.x;      // NUM_T * 512 float4s
    int t = idx >> 9;
    int c = idx & 511;                             // float4 index within row
    if (t >= NUM_T) return;

    int poff[NUM_E];
    {
        int off = 0;
#pragma unroll
        for (int k = 0; k < NUM_E; k++) {
            poff[k] = off;
            off += ((g_cnt[k] + BM - 1) / BM) * BM;
        }
    }

    int   e0 = g_tk_e[2 * t + 0], p0 = g_tk_pos[2 * t + 0];
    int   e1 = g_tk_e[2 * t + 1], p1 = g_tk_pos[2 * t + 1];
    float w0 = g_tk_w[2 * t + 0], w1 = g_tk_w[2 * t + 1];

    const uint2* ya = reinterpret_cast<const uint2*>(g_y + (size_t)(poff[e0] + p0) * DIM_H);
    const uint2* yb = reinterpret_cast<const uint2*>(g_y + (size_t)(poff[e1] + p1) * DIM_H);
    uint2 ua = __ldg(&ya[c]);
    uint2 ub = __ldg(&yb[c]);

    float2 a0 = __half22float2(*reinterpret_cast<__half2*>(&ua.x));
    float2 a1 = __half22float2(*reinterpret_cast<__half2*>(&ua.y));
    float2 b0 = __half22float2(*reinterpret_cast<__half2*>(&ub.x));
    float2 b1 = __half22float2(*reinterpret_cast<__half2*>(&ub.y));

    float4 o;
    o.x = w0 * a0.x + w1 * b0.x;
    o.y = w0 * a0.y + w1 * b0.y;
    o.z = w0 * a1.x + w1 * b1.x;
    o.w = w0 * a1.y + w1 * b1.y;
    reinterpret_cast<float4*>(out)[(size_t)t * 512 + c] = o;
}

// ============================================================
// Launch: fork convert_w onto a side stream so it overlaps
// router+gatherx; join before the GEMM.
// ============================================================
extern "C" void kernel_launch(void* const* d_in, const int* in_sizes, int n_in,
                              void* d_out, int out_size) {
    const float* x  = (const float*)d_in[0];   // [8192, 2048]
    const float* gw = (const float*)d_in[1];   // [8, 2048]
    const float* ew = (const float*)d_in[2];   // [8, 2048, 2048]
    float* out = (float*)d_out;
    float* logits = out + ((size_t)out_size - (size_t)NUM_T * NUM_E);

    static cudaStream_t s1 = nullptr;
    static cudaEvent_t ev_fork = nullptr, ev_join = nullptr;
    static int inited = 0;
    if (!inited) {
        cudaFuncSetAttribute(moe_gemm_kernel,
                             cudaFuncAttributeMaxDynamicSharedMemorySize, GEMM_SMEM);
        cudaStreamCreateWithFlags(&s1, cudaStreamNonBlocking);
        cudaEventCreateWithFlags(&ev_fork, cudaEventDisableTiming);
        cudaEventCreateWithFlags(&ev_join, cudaEventDisableTiming);
        inited = 1;
    }

    init_kernel<<<1, 32>>>();

    // fork: convert_w runs on s1 concurrently with router+gatherx
    cudaEventRecord(ev_fork, 0);
    cudaStreamWaitEvent(s1, ev_fork, 0);
    convert_w_kernel<<<(NUM_E * DIM_H * DIM_H / 4) / 256, 256, 0, s1>>>(ew);
    cudaEventRecord(ev_join, s1);

    router_kernel<<<NUM_T / 8, 256>>>(x, gw, logits);
    gatherx_kernel<<<PADT, 256>>>(x);

    // join: GEMM needs both branches
    cudaStreamWaitEvent(0, ev_join, 0);
    moe_gemm_kernel<<<GEMM_CTAS, 256, GEMM_SMEM>>>();
    combine_kernel<<<(NUM_T * 512) / 256, 256>>>(out);
}

// round 16
// speedup vs baseline: 1.2422x; 1.2422x over previous
#include <cuda_runtime.h>
#include <cuda_fp16.h>
#include <cstdint>

// ============================================================
// Problem constants
// ============================================================
#define NUM_T 8192
#define DIM_H 2048
#define NUM_E 8
#define PADT  17408          // padded slot capacity (prefix layout, y only)

// GEMM tile: 128x128 CTA, 8 warps of 64x32, 2 CTAs/SM (4 warps/SMSP)
#define BM 128
#define BN 128
#define BK 64                // 64 fp16 = 128 B = one swizzled row
#define STAGES 3
#define NT_TILES (DIM_H / BN)   // 16
#define MAX_MT 136              // sum ceil(cnt_e/128) <= 128+7

// ============================================================
// Device scratch (allocation-free rule: static __device__ arrays)
// ============================================================
__device__ int   g_cnt[NUM_E];
__device__ int   g_toklist[NUM_E * NUM_T];
__device__ int   g_tk_e[NUM_T * 2];
__device__ int   g_tk_pos[NUM_T * 2];
__device__ float g_tk_w[NUM_T * 2];
__device__ __half g_wh[(size_t)NUM_E * DIM_H * DIM_H];   // 67 MB fp16 weights
__device__ __half g_xtok[(size_t)NUM_T * DIM_H];         // 34 MB token-major fp16 x
__device__ __half g_y[(size_t)PADT * DIM_H];             // expert outputs (fp16)

// ============================================================
// PTX helpers (base sm_103-safe: sm_80-era instructions only)
// ============================================================
__device__ __forceinline__ uint32_t smem_to_u32(const void* p) {
    uint32_t a;
    asm("{ .reg .u64 t; cvta.to.shared.u64 t, %1; cvt.u32.u64 %0, t; }" : "=r"(a) : "l"(p));
    return a;
}

#define CP_ASYNC16(s, g) \
    asm volatile("cp.async.cg.shared.global [%0], [%1], 16;" :: "r"(s), "l"(g))
#define CP_COMMIT() asm volatile("cp.async.commit_group;" ::: "memory")
#define CP_WAIT(n)  asm volatile("cp.async.wait_group %0;" :: "n"(n) : "memory")

__device__ __forceinline__ void ldsm_x4(uint32_t (&r)[4], uint32_t addr) {
    asm volatile("ldmatrix.sync.aligned.m8n8.x4.shared.b16 {%0,%1,%2,%3}, [%4];"
        : "=r"(r[0]), "=r"(r[1]), "=r"(r[2]), "=r"(r[3]) : "r"(addr));
}
__device__ __forceinline__ void mma16816(float (&d)[4], const uint32_t (&a)[4],
                                         uint32_t b0, uint32_t b1) {
    asm volatile(
        "mma.sync.aligned.m16n8k16.row.col.f32.f16.f16.f32 "
        "{%0,%1,%2,%3}, {%4,%5,%6,%7}, {%8,%9}, {%0,%1,%2,%3};"
        : "+f"(d[0]), "+f"(d[1]), "+f"(d[2]), "+f"(d[3])
        : "r"(a[0]), "r"(a[1]), "r"(a[2]), "r"(a[3]), "r"(b0), "r"(b1));
}

// ============================================================
// Kernel 1: zero counters
// ============================================================
__global__ void init_kernel() {
    if (threadIdx.x < NUM_E) g_cnt[threadIdx.x] = 0;
}

// ============================================================
// Kernel 2: router (one warp per token)
// logits -> d_out tail; top-2 -> toklist; fp16 row -> g_xtok (token-major)
// ============================================================
__global__ __launch_bounds__(256) void router_kernel(
    const float* __restrict__ x, const float* __restrict__ gw,
    float* __restrict__ logits_out)
{
    int gwarp = (blockIdx.x * blockDim.x + threadIdx.x) >> 5;
    int lane  = threadIdx.x & 31;
    if (gwarp >= NUM_T) return;
    int t = gwarp;

    const float4* xr = reinterpret_cast<const float4*>(x + (size_t)t * DIM_H);
    const float4* g4 = reinterpret_cast<const float4*>(gw);
    uint2* xo = reinterpret_cast<uint2*>(g_xtok + (size_t)t * DIM_H);

    float acc[NUM_E];
#pragma unroll
    for (int e = 0; e < NUM_E; e++) acc[e] = 0.f;

#pragma unroll 4
    for (int i = 0; i < 16; i++) {
        float4 xv = __ldg(&xr[lane + i * 32]);
        // fp16 copy for the GEMM A-path (token-major, coalesced)
        __half2 h0 = __floats2half2_rn(xv.x, xv.y);
        __half2 h1 = __floats2half2_rn(xv.z, xv.w);
        uint2 pk;
        pk.x = *reinterpret_cast<uint32_t*>(&h0);
        pk.y = *reinterpret_cast<uint32_t*>(&h1);
        xo[lane + i * 32] = pk;
#pragma unroll
        for (int e = 0; e < NUM_E; e++) {
            float4 gv = __ldg(&g4[e * 512 + lane + i * 32]);
            acc[e] += xv.x * gv.x + xv.y * gv.y + xv.z * gv.z + xv.w * gv.w;
        }
    }
#pragma unroll
    for (int e = 0; e < NUM_E; e++) {
#pragma unroll
        for (int o = 16; o > 0; o >>= 1)
            acc[e] += __shfl_xor_sync(0xFFFFFFFFu, acc[e], o);
    }

    if (lane == 0) {
        float* lo = logits_out + (size_t)t * NUM_E;
#pragma unroll
        for (int e = 0; e < NUM_E; e++) lo[e] = acc[e];

        int e1 = 0; float l1 = acc[0];
#pragma unroll
        for (int e = 1; e < NUM_E; e++) if (acc[e] > l1) { l1 = acc[e]; e1 = e; }
        int e2 = -1; float l2 = -3.4e38f;
#pragma unroll
        for (int e = 0; e < NUM_E; e++) if (e != e1 && acc[e] > l2) { l2 = acc[e]; e2 = e; }

        float w1 = 1.0f / (1.0f + expf(l2 - l1));   // sigmoid(l1-l2)
        float w2 = 1.0f - w1;

        int p1 = atomicAdd(&g_cnt[e1], 1);
        g_toklist[e1 * NUM_T + p1] = t;
        g_tk_e[2 * t + 0] = e1; g_tk_pos[2 * t + 0] = p1; g_tk_w[2 * t + 0] = w1;

        int p2 = atomicAdd(&g_cnt[e2], 1);
        g_toklist[e2 * NUM_T + p2] = t;
        g_tk_e[2 * t + 1] = e2; g_tk_pos[2 * t + 1] = p2; g_tk_w[2 * t + 1] = w2;
    }
}

// ============================================================
// Kernel 3: convert W fp32 -> fp16 (runs on forked stream)
// ============================================================
__global__ __launch_bounds__(256) void convert_w_kernel(const float* __restrict__ ew) {
    size_t i = (size_t)blockIdx.x * 256 + threadIdx.x;  // float4 index
    float4 v = __ldg(reinterpret_cast<const float4*>(ew) + i);
    __half2* o = reinterpret_cast<__half2*>(g_wh) + 2 * i;
    o[0] = __floats2half2_rn(v.x, v.y);
    o[1] = __floats2half2_rn(v.z, v.w);
}

// ============================================================
// Kernel 4: pipelined mma.sync GEMM with gather-on-load A path
// CTA tile 128x128, K-stage 64, 3-stage cp.async,
// 8 warps of 64x32 (4 warps/SMSP at 2 CTAs/SM).
// A rows resolved from toklist via smem row-pointer table.
// Pad rows clamp to token 0 (their y rows are never read).
// ============================================================
#define SM_A 0
#define SM_B (BM * 128)                    // 16384
#define STAGE_BYTES (BM * 128 + BN * 128)  // 32768
#define GEMM_SMEM (STAGES * STAGE_BYTES)   // 98304

__device__ __forceinline__ void issue_stage(
    uint32_t sbase, const __half* const* arow, const __half* Bw, int koff, int tid)
{
#pragma unroll
    for (int i = 0; i < 4; i++) {
        int ch = tid + i * 256;
        int row = ch >> 3, c = ch & 7;
        uint32_t soff = row * 128 + ((c ^ (row & 7)) * 16);
        const char* ga = (const char*)(arow[row] + koff) + c * 16;
        CP_ASYNC16(sbase + SM_A + soff, ga);
    }
#pragma unroll
    for (int i = 0; i < 4; i++) {
        int ch = tid + i * 256;
        int row = ch >> 3, c = ch & 7;
        uint32_t soff = row * 128 + ((c ^ (row & 7)) * 16);
        const char* gb = (const char*)(Bw + (size_t)row * DIM_H + koff) + c * 16;
        CP_ASYNC16(sbase + SM_B + soff, gb);
    }
    CP_COMMIT();
}

__global__ __launch_bounds__(256, 2) void moe_gemm_kernel() {
    int ntile = blockIdx.x;
    int mtile = blockIdx.y;

    // inline tile table: find expert owning this mtile
    int e = -1, mrow = 0, local0 = 0, cnt_e = 0;
    {
        int tacc = 0, off = 0;
#pragma unroll
        for (int k = 0; k < NUM_E; k++) {
            int cnt = g_cnt[k];
            int tiles = (cnt + BM - 1) / BM;
            if (e < 0 && mtile < tacc + tiles) {
                e = k; local0 = (mtile - tacc) * BM; mrow = off + local0; cnt_e = cnt;
            }
            tacc += tiles;
            off += tiles * BM;
        }
        if (e < 0) return;   // beyond live tiles
    }

    extern __shared__ char smem[];
    __shared__ const __half* s_arow[BM];    // per-row gathered A base pointers
    uint32_t sb = smem_to_u32(smem);
    int tid = threadIdx.x, wid = tid >> 5, lane = tid & 31;

    if (tid < BM) {
        int local = local0 + tid;
        int tok = (local < cnt_e) ? g_toklist[e * NUM_T + local] : 0;  // clamp: pad y unread
        s_arow[tid] = g_xtok + (size_t)tok * DIM_H;
    }
    __syncthreads();

    const __half* Bw = g_wh + (size_t)e * DIM_H * DIM_H + (size_t)(ntile * BN) * DIM_H;

    // prologue
#pragma unroll
    for (int s = 0; s < STAGES - 1; s++)
        issue_stage(sb + s * STAGE_BYTES, s_arow, Bw, s * BK, tid);

    // warp tile 64x32: acc[4 mf][4 nf][4]
    float acc[4][4][4];
#pragma unroll
    for (int a = 0; a < 4; a++)
#pragma unroll
        for (int b = 0; b < 4; b++)
#pragma unroll
            for (int c = 0; c < 4; c++) acc[a][b][c] = 0.f;

    int wm0 = (wid & 1) * 64;
    int wn0 = (wid >> 1) * 32;
    int lrow = lane & 15;
    int lhalf = lane >> 4;

    const int KT = DIM_H / BK;   // 32
    for (int kc = 0; kc < KT; kc++) {
        CP_WAIT(STAGES - 2);
        __syncthreads();
        uint32_t sbase = sb + (kc % STAGES) * STAGE_BYTES;

        if (kc + STAGES - 1 < KT)
            issue_stage(sb + ((kc + STAGES - 1) % STAGES) * STAGE_BYTES,
                        s_arow, Bw, (kc + STAGES - 1) * BK, tid);
        else
            CP_COMMIT();   // keep group accounting uniform

#pragma unroll
        for (int ks = 0; ks < 4; ks++) {
            uint32_t ah[4][4], bf[2][4];
            int c = ks * 2 + lhalf;
#pragma unroll
            for (int mf = 0; mf < 4; mf++) {
                int row = wm0 + mf * 16 + lrow;
                ldsm_x4(ah[mf], sbase + SM_A + row * 128 + ((c ^ (row & 7)) * 16));
            }
#pragma unroll
            for (int nb = 0; nb < 2; nb++) {
                int row = wn0 + nb * 16 + lrow;
                ldsm_x4(bf[nb], sbase + SM_B + row * 128 + ((c ^ (row & 7)) * 16));
            }
#pragma unroll
            for (int mf = 0; mf < 4; mf++)
#pragma unroll
                for (int nb = 0; nb < 2; nb++) {
                    mma16816(acc[mf][2 * nb],     ah[mf], bf[nb][0], bf[nb][2]);
                    mma16816(acc[mf][2 * nb + 1], ah[mf], bf[nb][1], bf[nb][3]);
                }
        }
    }

    // epilogue: fp16 half2 stores into g_y (compact padded slot layout)
    int r0 = lane >> 2;
    int c0 = (lane & 3) * 2;
#pragma unroll
    for (int mf = 0; mf < 4; mf++)
#pragma unroll
        for (int nf = 0; nf < 4; nf++)
#pragma unroll
            for (int h = 0; h < 2; h++) {
                int row = mrow + wm0 + mf * 16 + r0 + 8 * h;
                int col = ntile * BN + wn0 + nf * 8 + c0;
                __half2 v = __floats2half2_rn(acc[mf][nf][2 * h], acc[mf][nf][2 * h + 1]);
                *reinterpret_cast<__half2*>(g_y + (size_t)row * DIM_H + col) = v;
            }
}

// ============================================================
// Kernel 5: combine fp16 y slots into final fp32 out
// (prefix offsets computed inline from g_cnt; uniform L1-hit loads)
// ============================================================
__global__ __launch_bounds__(256) void combine_kernel(float* __restrict__ out) {
    int idx = blockIdx.x * 256 + threadIdx.x;      // NUM_T * 512 float4s
    int t = idx >> 9;
    int c = idx & 511;                             // float4 index within row
    if (t >= NUM_T) return;

    int poff[NUM_E];
    {
        int off = 0;
#pragma unroll
        for (int k = 0; k < NUM_E; k++) {
            poff[k] = off;
            off += ((g_cnt[k] + BM - 1) / BM) * BM;
        }
    }

    int   e0 = g_tk_e[2 * t + 0], p0 = g_tk_pos[2 * t + 0];
    int   e1 = g_tk_e[2 * t + 1], p1 = g_tk_pos[2 * t + 1];
    float w0 = g_tk_w[2 * t + 0], w1 = g_tk_w[2 * t + 1];

    const uint2* ya = reinterpret_cast<const uint2*>(g_y + (size_t)(poff[e0] + p0) * DIM_H);
    const uint2* yb = reinterpret_cast<const uint2*>(g_y + (size_t)(poff[e1] + p1) * DIM_H);
    uint2 ua = __ldg(&ya[c]);
    uint2 ub = __ldg(&yb[c]);

    float2 a0 = __half22float2(*reinterpret_cast<__half2*>(&ua.x));
    float2 a1 = __half22float2(*reinterpret_cast<__half2*>(&ua.y));
    float2 b0 = __half22float2(*reinterpret_cast<__half2*>(&ub.x));
    float2 b1 = __half22float2(*reinterpret_cast<__half2*>(&ub.y));

    float4 o;
    o.x = w0 * a0.x + w1 * b0.x;
    o.y = w0 * a0.y + w1 * b0.y;
    o.z = w0 * a1.x + w1 * b1.x;
    o.w = w0 * a1.y + w1 * b1.y;
    reinterpret_cast<float4*>(out)[(size_t)t * 512 + c] = o;
}

// ============================================================
// Launch: fork convert_w onto a side stream so it overlaps the
// (fatter) router; join before the GEMM. No gatherx kernel.
// ============================================================
extern "C" void kernel_launch(void* const* d_in, const int* in_sizes, int n_in,
                              void* d_out, int out_size) {
    const float* x  = (const float*)d_in[0];   // [8192, 2048]
    const float* gw = (const float*)d_in[1];   // [8, 2048]
    const float* ew = (const float*)d_in[2];   // [8, 2048, 2048]
    float* out = (float*)d_out;
    float* logits = out + ((size_t)out_size - (size_t)NUM_T * NUM_E);

    static cudaStream_t s1 = nullptr;
    static cudaEvent_t ev_fork = nullptr, ev_join = nullptr;
    static int inited = 0;
    if (!inited) {
        cudaFuncSetAttribute(moe_gemm_kernel,
                             cudaFuncAttributeMaxDynamicSharedMemorySize, GEMM_SMEM);
        cudaStreamCreateWithFlags(&s1, cudaStreamNonBlocking);
        cudaEventCreateWithFlags(&ev_fork, cudaEventDisableTiming);
        cudaEventCreateWithFlags(&ev_join, cudaEventDisableTiming);
        inited = 1;
    }

    init_kernel<<<1, 32>>>();

    // fork: convert_w runs on s1 concurrently with router
    cudaEventRecord(ev_fork, 0);
    cudaStreamWaitEvent(s1, ev_fork, 0);
    convert_w_kernel<<<(NUM_E * DIM_H * DIM_H / 4) / 256, 256, 0, s1>>>(ew);
    cudaEventRecord(ev_join, s1);

    router_kernel<<<NUM_T / 8, 256>>>(x, gw, logits);

    // join: GEMM needs both branches
    cudaStreamWaitEvent(0, ev_join, 0);
    moe_gemm_kernel<<<dim3(NT_TILES, MAX_MT), 256, GEMM_SMEM>>>();
    combine_kernel<<<(NUM_T * 512) / 256, 256>>>(out);
}

// round 17
// speedup vs baseline: 1.2649x; 1.0183x over previous
#include <cuda_runtime.h>
#include <cuda_fp16.h>
#include <cstdint>

// ============================================================
// Problem constants
// ============================================================
#define NUM_T 8192
#define DIM_H 2048
#define NUM_E 8
#define PADT  17408          // padded slot capacity (prefix layout, y only)

// GEMM tile: 128x128 CTA, 8 warps of 64x32, 2 CTAs/SM (4 warps/SMSP)
#define BM 128
#define BN 128
#define BK 64                // 64 fp16 = 128 B = one swizzled row
#define STAGES 3
#define NT_TILES (DIM_H / BN)   // 16
#define NT_HALF  (NT_TILES / 2) // 8 per split
#define MAX_MT 136              // sum ceil(cnt_e/128) <= 128+7

// ============================================================
// Device scratch (allocation-free rule: static __device__ arrays)
// ============================================================
__device__ int   g_cnt[NUM_E];
__device__ int   g_toklist[NUM_E * NUM_T];
__device__ int   g_tk_e[NUM_T * 2];
__device__ int   g_tk_pos[NUM_T * 2];
__device__ float g_tk_w[NUM_T * 2];
__device__ __half g_wh[(size_t)NUM_E * DIM_H * DIM_H];   // 67 MB fp16 weights
__device__ __half g_xtok[(size_t)NUM_T * DIM_H];         // 34 MB token-major fp16 x
__device__ __half g_y[(size_t)PADT * DIM_H];             // expert outputs (fp16)

// ============================================================
// PTX helpers (base sm_103-safe: sm_80-era instructions only)
// ============================================================
__device__ __forceinline__ uint32_t smem_to_u32(const void* p) {
    uint32_t a;
    asm("{ .reg .u64 t; cvta.to.shared.u64 t, %1; cvt.u32.u64 %0, t; }" : "=r"(a) : "l"(p));
    return a;
}

#define CP_ASYNC16(s, g) \
    asm volatile("cp.async.cg.shared.global [%0], [%1], 16;" :: "r"(s), "l"(g))
#define CP_COMMIT() asm volatile("cp.async.commit_group;" ::: "memory")
#define CP_WAIT(n)  asm volatile("cp.async.wait_group %0;" :: "n"(n) : "memory")

__device__ __forceinline__ void ldsm_x4(uint32_t (&r)[4], uint32_t addr) {
    asm volatile("ldmatrix.sync.aligned.m8n8.x4.shared.b16 {%0,%1,%2,%3}, [%4];"
        : "=r"(r[0]), "=r"(r[1]), "=r"(r[2]), "=r"(r[3]) : "r"(addr));
}
__device__ __forceinline__ void mma16816(float (&d)[4], const uint32_t (&a)[4],
                                         uint32_t b0, uint32_t b1) {
    asm volatile(
        "mma.sync.aligned.m16n8k16.row.col.f32.f16.f16.f32 "
        "{%0,%1,%2,%3}, {%4,%5,%6,%7}, {%8,%9}, {%0,%1,%2,%3};"
        : "+f"(d[0]), "+f"(d[1]), "+f"(d[2]), "+f"(d[3])
        : "r"(a[0]), "r"(a[1]), "r"(a[2]), "r"(a[3]), "r"(b0), "r"(b1));
}

// ============================================================
// Kernel 1: zero counters
// ============================================================
__global__ void init_kernel() {
    if (threadIdx.x < NUM_E) g_cnt[threadIdx.x] = 0;
}

// ============================================================
// Kernel 2: router (one warp per token)
// logits -> d_out tail; top-2 -> toklist; fp16 row -> g_xtok (token-major)
// ============================================================
__global__ __launch_bounds__(256) void router_kernel(
    const float* __restrict__ x, const float* __restrict__ gw,
    float* __restrict__ logits_out)
{
    int gwarp = (blockIdx.x * blockDim.x + threadIdx.x) >> 5;
    int lane  = threadIdx.x & 31;
    if (gwarp >= NUM_T) return;
    int t = gwarp;

    const float4* xr = reinterpret_cast<const float4*>(x + (size_t)t * DIM_H);
    const float4* g4 = reinterpret_cast<const float4*>(gw);
    uint2* xo = reinterpret_cast<uint2*>(g_xtok + (size_t)t * DIM_H);

    float acc[NUM_E];
#pragma unroll
    for (int e = 0; e < NUM_E; e++) acc[e] = 0.f;

#pragma unroll 4
    for (int i = 0; i < 16; i++) {
        float4 xv = __ldg(&xr[lane + i * 32]);
        __half2 h0 = __floats2half2_rn(xv.x, xv.y);
        __half2 h1 = __floats2half2_rn(xv.z, xv.w);
        uint2 pk;
        pk.x = *reinterpret_cast<uint32_t*>(&h0);
        pk.y = *reinterpret_cast<uint32_t*>(&h1);
        xo[lane + i * 32] = pk;
#pragma unroll
        for (int e = 0; e < NUM_E; e++) {
            float4 gv = __ldg(&g4[e * 512 + lane + i * 32]);
            acc[e] += xv.x * gv.x + xv.y * gv.y + xv.z * gv.z + xv.w * gv.w;
        }
    }
#pragma unroll
    for (int e = 0; e < NUM_E; e++) {
#pragma unroll
        for (int o = 16; o > 0; o >>= 1)
            acc[e] += __shfl_xor_sync(0xFFFFFFFFu, acc[e], o);
    }

    if (lane == 0) {
        float* lo = logits_out + (size_t)t * NUM_E;
#pragma unroll
        for (int e = 0; e < NUM_E; e++) lo[e] = acc[e];

        int e1 = 0; float l1 = acc[0];
#pragma unroll
        for (int e = 1; e < NUM_E; e++) if (acc[e] > l1) { l1 = acc[e]; e1 = e; }
        int e2 = -1; float l2 = -3.4e38f;
#pragma unroll
        for (int e = 0; e < NUM_E; e++) if (e != e1 && acc[e] > l2) { l2 = acc[e]; e2 = e; }

        float w1 = 1.0f / (1.0f + expf(l2 - l1));   // sigmoid(l1-l2)
        float w2 = 1.0f - w1;

        int p1 = atomicAdd(&g_cnt[e1], 1);
        g_toklist[e1 * NUM_T + p1] = t;
        g_tk_e[2 * t + 0] = e1; g_tk_pos[2 * t + 0] = p1; g_tk_w[2 * t + 0] = w1;

        int p2 = atomicAdd(&g_cnt[e2], 1);
        g_toklist[e2 * NUM_T + p2] = t;
        g_tk_e[2 * t + 1] = e2; g_tk_pos[2 * t + 1] = p2; g_tk_w[2 * t + 1] = w2;
    }
}

// ============================================================
// Kernel 3: convert W fp32 -> fp16 (runs on forked stream)
// ============================================================
__global__ __launch_bounds__(256) void convert_w_kernel(const float* __restrict__ ew) {
    size_t i = (size_t)blockIdx.x * 256 + threadIdx.x;  // float4 index
    float4 v = __ldg(reinterpret_cast<const float4*>(ew) + i);
    __half2* o = reinterpret_cast<__half2*>(g_wh) + 2 * i;
    o[0] = __floats2half2_rn(v.x, v.y);
    o[1] = __floats2half2_rn(v.z, v.w);
}

// ============================================================
// Kernel 4: pipelined mma.sync GEMM with gather-on-load A path
// Column-split: processes ntiles [ntile_base, ntile_base + NT_HALF).
// CTA tile 128x128, K-stage 64, 3-stage cp.async, 8 warps of 64x32.
// ============================================================
#define SM_A 0
#define SM_B (BM * 128)                    // 16384
#define STAGE_BYTES (BM * 128 + BN * 128)  // 32768
#define GEMM_SMEM (STAGES * STAGE_BYTES)   // 98304

__device__ __forceinline__ void issue_stage(
    uint32_t sbase, const __half* const* arow, const __half* Bw, int koff, int tid)
{
#pragma unroll
    for (int i = 0; i < 4; i++) {
        int ch = tid + i * 256;
        int row = ch >> 3, c = ch & 7;
        uint32_t soff = row * 128 + ((c ^ (row & 7)) * 16);
        const char* ga = (const char*)(arow[row] + koff) + c * 16;
        CP_ASYNC16(sbase + SM_A + soff, ga);
    }
#pragma unroll
    for (int i = 0; i < 4; i++) {
        int ch = tid + i * 256;
        int row = ch >> 3, c = ch & 7;
        uint32_t soff = row * 128 + ((c ^ (row & 7)) * 16);
        const char* gb = (const char*)(Bw + (size_t)row * DIM_H + koff) + c * 16;
        CP_ASYNC16(sbase + SM_B + soff, gb);
    }
    CP_COMMIT();
}

__global__ __launch_bounds__(256, 2) void moe_gemm_kernel(int ntile_base) {
    int ntile = ntile_base + blockIdx.x;
    int mtile = blockIdx.y;

    // inline tile table: find expert owning this mtile
    int e = -1, mrow = 0, local0 = 0, cnt_e = 0;
    {
        int tacc = 0, off = 0;
#pragma unroll
        for (int k = 0; k < NUM_E; k++) {
            int cnt = g_cnt[k];
            int tiles = (cnt + BM - 1) / BM;
            if (e < 0 && mtile < tacc + tiles) {
                e = k; local0 = (mtile - tacc) * BM; mrow = off + local0; cnt_e = cnt;
            }
            tacc += tiles;
            off += tiles * BM;
        }
        if (e < 0) return;   // beyond live tiles
    }

    extern __shared__ char smem[];
    __shared__ const __half* s_arow[BM];    // per-row gathered A base pointers
    uint32_t sb = smem_to_u32(smem);
    int tid = threadIdx.x, wid = tid >> 5, lane = tid & 31;

    if (tid < BM) {
        int local = local0 + tid;
        int tok = (local < cnt_e) ? g_toklist[e * NUM_T + local] : 0;  // clamp: pad y unread
        s_arow[tid] = g_xtok + (size_t)tok * DIM_H;
    }
    __syncthreads();

    const __half* Bw = g_wh + (size_t)e * DIM_H * DIM_H + (size_t)(ntile * BN) * DIM_H;

    // prologue
#pragma unroll
    for (int s = 0; s < STAGES - 1; s++)
        issue_stage(sb + s * STAGE_BYTES, s_arow, Bw, s * BK, tid);

    // warp tile 64x32: acc[4 mf][4 nf][4]
    float acc[4][4][4];
#pragma unroll
    for (int a = 0; a < 4; a++)
#pragma unroll
        for (int b = 0; b < 4; b++)
#pragma unroll
            for (int c = 0; c < 4; c++) acc[a][b][c] = 0.f;

    int wm0 = (wid & 1) * 64;
    int wn0 = (wid >> 1) * 32;
    int lrow = lane & 15;
    int lhalf = lane >> 4;

    const int KT = DIM_H / BK;   // 32
    for (int kc = 0; kc < KT; kc++) {
        CP_WAIT(STAGES - 2);
        __syncthreads();
        uint32_t sbase = sb + (kc % STAGES) * STAGE_BYTES;

        if (kc + STAGES - 1 < KT)
            issue_stage(sb + ((kc + STAGES - 1) % STAGES) * STAGE_BYTES,
                        s_arow, Bw, (kc + STAGES - 1) * BK, tid);
        else
            CP_COMMIT();   // keep group accounting uniform

#pragma unroll
        for (int ks = 0; ks < 4; ks++) {
            uint32_t ah[4][4], bf[2][4];
            int c = ks * 2 + lhalf;
#pragma unroll
            for (int mf = 0; mf < 4; mf++) {
                int row = wm0 + mf * 16 + lrow;
                ldsm_x4(ah[mf], sbase + SM_A + row * 128 + ((c ^ (row & 7)) * 16));
            }
#pragma unroll
            for (int nb = 0; nb < 2; nb++) {
                int row = wn0 + nb * 16 + lrow;
                ldsm_x4(bf[nb], sbase + SM_B + row * 128 + ((c ^ (row & 7)) * 16));
            }
#pragma unroll
            for (int mf = 0; mf < 4; mf++)
#pragma unroll
                for (int nb = 0; nb < 2; nb++) {
                    mma16816(acc[mf][2 * nb],     ah[mf], bf[nb][0], bf[nb][2]);
                    mma16816(acc[mf][2 * nb + 1], ah[mf], bf[nb][1], bf[nb][3]);
                }
        }
    }

    // epilogue: fp16 half2 stores into g_y (compact padded slot layout)
    int r0 = lane >> 2;
    int c0 = (lane & 3) * 2;
#pragma unroll
    for (int mf = 0; mf < 4; mf++)
#pragma unroll
        for (int nf = 0; nf < 4; nf++)
#pragma unroll
            for (int h = 0; h < 2; h++) {
                int row = mrow + wm0 + mf * 16 + r0 + 8 * h;
                int col = ntile * BN + wn0 + nf * 8 + c0;
                __half2 v = __floats2half2_rn(acc[mf][nf][2 * h], acc[mf][nf][2 * h + 1]);
                *reinterpret_cast<__half2*>(g_y + (size_t)row * DIM_H + col) = v;
            }
}

// ============================================================
// Kernel 5: combine fp16 y slots into final fp32 out
// Column-split: processes float4 col indices [cbase, cbase+256).
// ============================================================
__global__ __launch_bounds__(256) void combine_kernel(float* __restrict__ out, int cbase) {
    int idx = blockIdx.x * 256 + threadIdx.x;      // NUM_T * 256 float4s per half
    int t = idx >> 8;
    int c = cbase + (idx & 255);                   // float4 index within row
    if (t >= NUM_T) return;

    int poff[NUM_E];
    {
        int off = 0;
#pragma unroll
        for (int k = 0; k < NUM_E; k++) {
            poff[k] = off;
            off += ((g_cnt[k] + BM - 1) / BM) * BM;
        }
    }

    int   e0 = g_tk_e[2 * t + 0], p0 = g_tk_pos[2 * t + 0];
    int   e1 = g_tk_e[2 * t + 1], p1 = g_tk_pos[2 * t + 1];
    float w0 = g_tk_w[2 * t + 0], w1 = g_tk_w[2 * t + 1];

    const uint2* ya = reinterpret_cast<const uint2*>(g_y + (size_t)(poff[e0] + p0) * DIM_H);
    const uint2* yb = reinterpret_cast<const uint2*>(g_y + (size_t)(poff[e1] + p1) * DIM_H);
    uint2 ua = __ldg(&ya[c]);
    uint2 ub = __ldg(&yb[c]);

    float2 a0 = __half22float2(*reinterpret_cast<__half2*>(&ua.x));
    float2 a1 = __half22float2(*reinterpret_cast<__half2*>(&ua.y));
    float2 b0 = __half22float2(*reinterpret_cast<__half2*>(&ub.x));
    float2 b1 = __half22float2(*reinterpret_cast<__half2*>(&ub.y));

    float4 o;
    o.x = w0 * a0.x + w1 * b0.x;
    o.y = w0 * a0.y + w1 * b0.y;
    o.z = w0 * a1.x + w1 * b1.x;
    o.w = w0 * a1.y + w1 * b1.y;
    reinterpret_cast<float4*>(out)[(size_t)t * 512 + c] = o;
}

// ============================================================
// Launch graph:
//   s0: init -> router -> GEMM_A(ntiles 0-7) -> combineA(cols 0-1023) -> wait s2
//   s1: convert_w (forked after init)
//   s2: (after router + convert_w) GEMM_B(ntiles 8-15) -> combineB -> join s0
// combineA overlaps GEMM_B's second half; GEMM_B backfills GEMM_A's tail.
// ============================================================
extern "C" void kernel_launch(void* const* d_in, const int* in_sizes, int n_in,
                              void* d_out, int out_size) {
    const float* x  = (const float*)d_in[0];   // [8192, 2048]
    const float* gw = (const float*)d_in[1];   // [8, 2048]
    const float* ew = (const float*)d_in[2];   // [8, 2048, 2048]
    float* out = (float*)d_out;
    float* logits = out + ((size_t)out_size - (size_t)NUM_T * NUM_E);

    static cudaStream_t s1 = nullptr, s2 = nullptr;
    static cudaEvent_t ev_fork = nullptr, ev_join = nullptr, ev_r = nullptr, ev_b = nullptr;
    static int inited = 0;
    if (!inited) {
        cudaFuncSetAttribute(moe_gemm_kernel,
                             cudaFuncAttributeMaxDynamicSharedMemorySize, GEMM_SMEM);
        cudaStreamCreateWithFlags(&s1, cudaStreamNonBlocking);
        cudaStreamCreateWithFlags(&s2, cudaStreamNonBlocking);
        cudaEventCreateWithFlags(&ev_fork, cudaEventDisableTiming);
        cudaEventCreateWithFlags(&ev_join, cudaEventDisableTiming);
        cudaEventCreateWithFlags(&ev_r, cudaEventDisableTiming);
        cudaEventCreateWithFlags(&ev_b, cudaEventDisableTiming);
        inited = 1;
    }

    init_kernel<<<1, 32>>>();

    // fork: convert_w on s1, concurrent with router
    cudaEventRecord(ev_fork, 0);
    cudaStreamWaitEvent(s1, ev_fork, 0);
    convert_w_kernel<<<(NUM_E * DIM_H * DIM_H / 4) / 256, 256, 0, s1>>>(ew);
    cudaEventRecord(ev_join, s1);

    router_kernel<<<NUM_T / 8, 256>>>(x, gw, logits);
    cudaEventRecord(ev_r, 0);

    // GEMM_A on s0 (needs router via stream order + convert_w via event)
    cudaStreamWaitEvent(0, ev_join, 0);
    moe_gemm_kernel<<<dim3(NT_HALF, MAX_MT), 256, GEMM_SMEM>>>(0);

    // GEMM_B on s2 (needs router + convert_w)
    cudaStreamWaitEvent(s2, ev_r, 0);
    cudaStreamWaitEvent(s2, ev_join, 0);
    moe_gemm_kernel<<<dim3(NT_HALF, MAX_MT), 256, GEMM_SMEM, s2>>>(NT_HALF);

    // combineA overlaps GEMM_B; combineB after GEMM_B
    combine_kernel<<<(NUM_T * 256) / 256, 256>>>(out, 0);
    combine_kernel<<<(NUM_T * 256) / 256, 256, 0, s2>>>(out, 256);

    // join s2 back into the origin stream for capture completeness
    cudaEventRecord(ev_b, s2);
    cudaStreamWaitEvent(0, ev_b, 0);
}